// round 1
// baseline (speedup 1.0000x reference)
#include <cuda_runtime.h>

// Problem: B=128 batches, S=1024 tokens, H=768, C=150, N=8 nodes, sep id 3.
// One block per batch. fp32 throughout.
//
// Pipeline per block (batch b):
//   1. block scan of output_ids -> positions of first 8 separators (segments are
//      contiguous ranges because seg = cumsum(is_sep) is monotone).
//   2. segment means over contiguous token ranges -> mean[8][768] in smem.
//      Only reads tokens up to the 8th sep (~64-150 of 1024) => ~30MB HBM total.
//   3. g = mean @ W1  (GEMM1 factorization: diff@W1 = g_i - g_j).
//   4. x[p][c] = relu(g_i - g_j + b1) for all 64 pairs.
//   5. y = relu(x @ Wm + bm); out = y @ W2 + b2, with Wm/W2 resident in smem,
//      register-tiled 4x5 micro-tiles, fp32 FFMA.

#define B_   128
#define S_   1024
#define H_   768
#define C_   150
#define NN   8
#define SEPID 3
#define NTHR 480
#define KT   128

// shared memory layout (floats)
#define OFF_A     0        // 22500: Wm (phase2) / W1 k-tile 128x160=20480 (phase1)
#define OFF_B     22500    // 22500: W2
#define OFF_X     45000    // 9728 = 64*152 : x/y buffer (phase1: mean 8*768=6144)
#define OFF_G     54728    // 1200 : g[8][150]
#define OFF_B1    55928    // 152
#define OFF_BM    56080    // 152
#define OFF_B2    56232    // 152
#define OFF_SCAN  56384    // 256 ints
#define OFF_BND   56640    // 16 ints
#define SMEM_FLOATS 56656
#define SMEM_BYTES (SMEM_FLOATS * 4)   // 226624 <= 232448 opt-in limit

__global__ __launch_bounds__(NTHR, 1)
void grapher_kernel(const int* __restrict__ ids,
                    const float* __restrict__ feat,
                    const float* __restrict__ W1, const float* __restrict__ b1,
                    const float* __restrict__ Wm, const float* __restrict__ bm,
                    const float* __restrict__ W2, const float* __restrict__ b2,
                    float* __restrict__ out)
{
    extern __shared__ float sm[];
    float* sA  = sm + OFF_A;
    float* sB  = sm + OFF_B;
    float* sX  = sm + OFF_X;     // mean in phase1, x/y in phase2
    float* sG  = sm + OFF_G;
    float* sb1 = sm + OFF_B1;
    float* sbm = sm + OFF_BM;
    float* sb2 = sm + OFF_B2;
    int*   sScan = (int*)(sm + OFF_SCAN);
    int*   sBnd  = (int*)(sm + OFF_BND);

    const int tid = threadIdx.x;
    const int b   = blockIdx.x;

    // ---------------- 1. separator scan -> sBnd[1..8] = pos of k-th sep (or S) ----
    if (tid < 16) sBnd[tid] = S_;

    int myids[4];
    int cnt = 0;
    if (tid < 256) {
        const int* row = ids + b * S_ + tid * 4;
#pragma unroll
        for (int s = 0; s < 4; s++) { myids[s] = row[s]; cnt += (myids[s] == SEPID); }
        sScan[tid] = cnt;
    }
    __syncthreads();
#pragma unroll
    for (int off = 1; off < 256; off <<= 1) {
        int v = 0;
        if (tid < 256) {
            v = sScan[tid];
            if (tid >= off) v += sScan[tid - off];
        }
        __syncthreads();
        if (tid < 256) sScan[tid] = v;
        __syncthreads();
    }
    if (tid < 256) {
        int run = sScan[tid] - cnt;   // exclusive prefix count of seps
#pragma unroll
        for (int s = 0; s < 4; s++) {
            if (myids[s] == SEPID) {
                run++;
                if (run <= NN) sBnd[run] = tid * 4 + s;
            }
        }
    }
    __syncthreads();

    // ---------------- 2. segment means -> sX[n*768 + h] ----------------
    // node n tokens: ( (n==0 ? -1 : pos_n), pos_{n+1} ) exclusive of seps.
    if (tid < 384) {
        const float2* f2 = (const float2*)(feat + (size_t)b * S_ * H_);
        const int col = tid;              // float2 column, H/2 = 384
#pragma unroll 1
        for (int n = 0; n < NN; n++) {
            int lo = (n == 0) ? 0 : sBnd[n] + 1;
            int hi = sBnd[n + 1];
            float2 acc = make_float2(0.f, 0.f);
            for (int t = lo; t < hi; t++) {
                float2 v = f2[t * 384 + col];
                acc.x += v.x; acc.y += v.y;
            }
            int c = hi - lo; if (c < 1) c = 1;
            float inv = 1.0f / (float)c;
            sX[n * H_ + col * 2]     = acc.x * inv;
            sX[n * H_ + col * 2 + 1] = acc.y * inv;
        }
    } else {
        // spare threads load bias vectors
        for (int i = tid - 384; i < C_; i += 96) {
            sb1[i] = b1[i]; sbm[i] = bm[i]; sb2[i] = b2[i];
        }
    }
    __syncthreads();

    // ---------------- 3. g[n][c] = sum_h mean[n][h] * W1[h][c] ----------------
    // warps 0..7 compute (warp = n, lane -> 5 cols); W1 k-tiles in sA padded to 160.
    const int warp = tid >> 5, lane = tid & 31;
    const int gc0 = lane * 5;
    float accg[5] = {0.f, 0.f, 0.f, 0.f, 0.f};

    for (int kt = 0; kt < H_ / KT; kt++) {
        for (int i = tid; i < KT * 160; i += NTHR) {
            int k = i / 160;
            int c = i - k * 160;
            sA[i] = (c < C_) ? W1[(kt * KT + k) * C_ + c] : 0.f;
        }
        __syncthreads();
        if (warp < 8) {
            const float4* m4 = (const float4*)(sX + warp * H_ + kt * KT);
#pragma unroll 4
            for (int k4 = 0; k4 < KT / 4; k4++) {
                float4 m = m4[k4];
                const float* wr = sA + (k4 * 4) * 160 + gc0;
#pragma unroll
                for (int j = 0; j < 5; j++) accg[j] += m.x * wr[j];
#pragma unroll
                for (int j = 0; j < 5; j++) accg[j] += m.y * wr[160 + j];
#pragma unroll
                for (int j = 0; j < 5; j++) accg[j] += m.z * wr[320 + j];
#pragma unroll
                for (int j = 0; j < 5; j++) accg[j] += m.w * wr[480 + j];
            }
        }
        __syncthreads();
    }
    if (warp < 8) {
#pragma unroll
        for (int j = 0; j < 5; j++) {
            int c = gc0 + j;
            if (c < C_) sG[warp * C_ + c] = accg[j];
        }
    }

    // ---------------- load Wm, W2 into smem (overwrites W1 tile) ------------
    {
        const float4* wm4 = (const float4*)Wm;
        const float4* w24 = (const float4*)W2;
        float4* a4 = (float4*)sA;
        float4* b4 = (float4*)sB;
        for (int i = tid; i < (C_ * C_) / 4; i += NTHR) {  // 5625 float4
            a4[i] = wm4[i];
            b4[i] = w24[i];
        }
    }
    __syncthreads();

    // ---------------- 4. x[p][c] = relu(g_i - g_j + b1) ---------------------
    const int cg = tid % 30;      // 30 col-groups * 5 = 150
    const int rg = tid / 30;      // 16 row-groups * 4 = 64 pairs
    const int c0 = cg * 5, r0 = rg * 4;
#pragma unroll
    for (int rr = 0; rr < 4; rr++) {
        int p = r0 + rr;
        int i = p >> 3, j = p & 7;
#pragma unroll
        for (int cc = 0; cc < 5; cc++) {
            int c = c0 + cc;
            float v = sG[i * C_ + c] - sG[j * C_ + c] + sb1[c];
            sX[p * 152 + c] = fmaxf(v, 0.f);
        }
    }
    __syncthreads();

    // ---------------- 5a. y = relu(x @ Wm + bm) -----------------------------
    float acc[4][5];
#pragma unroll
    for (int rr = 0; rr < 4; rr++)
#pragma unroll
        for (int cc = 0; cc < 5; cc++) acc[rr][cc] = sbm[c0 + cc];

#pragma unroll 1
    for (int k2 = 0; k2 < C_ / 2; k2++) {
        float2 xv[4];
#pragma unroll
        for (int rr = 0; rr < 4; rr++)
            xv[rr] = *(const float2*)(sX + (r0 + rr) * 152 + 2 * k2);
#pragma unroll
        for (int cc = 0; cc < 5; cc++) {
            float w = sA[(2 * k2) * C_ + c0 + cc];
#pragma unroll
            for (int rr = 0; rr < 4; rr++) acc[rr][cc] += xv[rr].x * w;
        }
#pragma unroll
        for (int cc = 0; cc < 5; cc++) {
            float w = sA[(2 * k2 + 1) * C_ + c0 + cc];
#pragma unroll
            for (int rr = 0; rr < 4; rr++) acc[rr][cc] += xv[rr].y * w;
        }
    }
    __syncthreads();   // all x reads done
#pragma unroll
    for (int rr = 0; rr < 4; rr++)
#pragma unroll
        for (int cc = 0; cc < 5; cc++)
            sX[(r0 + rr) * 152 + c0 + cc] = fmaxf(acc[rr][cc], 0.f);
    __syncthreads();

    // ---------------- 5b. out = y @ W2 + b2 ---------------------------------
#pragma unroll
    for (int rr = 0; rr < 4; rr++)
#pragma unroll
        for (int cc = 0; cc < 5; cc++) acc[rr][cc] = sb2[c0 + cc];

#pragma unroll 1
    for (int k2 = 0; k2 < C_ / 2; k2++) {
        float2 xv[4];
#pragma unroll
        for (int rr = 0; rr < 4; rr++)
            xv[rr] = *(const float2*)(sX + (r0 + rr) * 152 + 2 * k2);
#pragma unroll
        for (int cc = 0; cc < 5; cc++) {
            float w = sB[(2 * k2) * C_ + c0 + cc];
#pragma unroll
            for (int rr = 0; rr < 4; rr++) acc[rr][cc] += xv[rr].x * w;
        }
#pragma unroll
        for (int cc = 0; cc < 5; cc++) {
            float w = sB[(2 * k2 + 1) * C_ + c0 + cc];
#pragma unroll
            for (int rr = 0; rr < 4; rr++) acc[rr][cc] += xv[rr].y * w;
        }
    }

    // out layout [i][j][b][c] : ((p*128 + b)*150 + c)
#pragma unroll
    for (int rr = 0; rr < 4; rr++) {
        int p = r0 + rr;
        float* o = out + ((size_t)p * B_ + b) * C_ + c0;
#pragma unroll
        for (int cc = 0; cc < 5; cc++) o[cc] = acc[rr][cc];
    }
}

extern "C" void kernel_launch(void* const* d_in, const int* in_sizes, int n_in,
                              void* d_out, int out_size)
{
    const int*   ids = (const int*)d_in[0];
    const float* feat = (const float*)d_in[1];
    const float* W1 = (const float*)d_in[2];
    const float* b1 = (const float*)d_in[3];
    const float* Wm = (const float*)d_in[4];
    const float* bm = (const float*)d_in[5];
    const float* W2 = (const float*)d_in[6];
    const float* b2 = (const float*)d_in[7];
    float* out = (float*)d_out;

    cudaFuncSetAttribute(grapher_kernel,
                         cudaFuncAttributeMaxDynamicSharedMemorySize, SMEM_BYTES);
    grapher_kernel<<<B_, NTHR, SMEM_BYTES>>>(ids, feat, W1, b1, Wm, bm, W2, b2, out);
}

// round 2
// speedup vs baseline: 1.0013x; 1.0013x over previous
#include <cuda_runtime.h>

// Problem: B=128 batches, S=1024 tokens, H=768, C=150, N=8 nodes, sep id 3.
// One block per batch. fp32 throughout.
//
// Pipeline per block (batch b):
//   1. block scan of output_ids -> positions of first 8 separators (segments are
//      contiguous ranges because seg = cumsum(is_sep) is monotone).
//   2. segment means over contiguous token ranges -> mean[8][768] in smem.
//      Only reads tokens up to the 8th sep (~64-150 of 1024) => ~30MB HBM total.
//   3. g = mean @ W1  (GEMM1 factorization: diff@W1 = g_i - g_j).
//   4. x[p][c] = relu(g_i - g_j + b1) for all 64 pairs.
//   5. y = relu(x @ Wm + bm); out = y @ W2 + b2, with Wm/W2 resident in smem,
//      register-tiled 4x5 micro-tiles, fp32 FFMA.

#define B_   128
#define S_   1024
#define H_   768
#define C_   150
#define NN   8
#define SEPID 3
#define NTHR 480
#define KT   128

// shared memory layout (floats)
#define OFF_A     0        // 22500: Wm (phase2) / W1 k-tile 128x160=20480 (phase1)
#define OFF_B     22500    // 22500: W2
#define OFF_X     45000    // 9728 = 64*152 : x/y buffer (phase1: mean 8*768=6144)
#define OFF_G     54728    // 1200 : g[8][150]
#define OFF_B1    55928    // 152
#define OFF_BM    56080    // 152
#define OFF_B2    56232    // 152
#define OFF_SCAN  56384    // 256 ints
#define OFF_BND   56640    // 16 ints
#define SMEM_FLOATS 56656
#define SMEM_BYTES (SMEM_FLOATS * 4)   // 226624 <= 232448 opt-in limit

__global__ __launch_bounds__(NTHR, 1)
void grapher_kernel(const int* __restrict__ ids,
                    const float* __restrict__ feat,
                    const float* __restrict__ W1, const float* __restrict__ b1,
                    const float* __restrict__ Wm, const float* __restrict__ bm,
                    const float* __restrict__ W2, const float* __restrict__ b2,
                    float* __restrict__ out)
{
    extern __shared__ float sm[];
    float* sA  = sm + OFF_A;
    float* sB  = sm + OFF_B;
    float* sX  = sm + OFF_X;     // mean in phase1, x/y in phase2
    float* sG  = sm + OFF_G;
    float* sb1 = sm + OFF_B1;
    float* sbm = sm + OFF_BM;
    float* sb2 = sm + OFF_B2;
    int*   sScan = (int*)(sm + OFF_SCAN);
    int*   sBnd  = (int*)(sm + OFF_BND);

    const int tid = threadIdx.x;
    const int b   = blockIdx.x;

    // ---------------- 1. separator scan -> sBnd[1..8] = pos of k-th sep (or S) ----
    if (tid < 16) sBnd[tid] = S_;

    int myids[4];
    int cnt = 0;
    if (tid < 256) {
        const int* row = ids + b * S_ + tid * 4;
#pragma unroll
        for (int s = 0; s < 4; s++) { myids[s] = row[s]; cnt += (myids[s] == SEPID); }
        sScan[tid] = cnt;
    }
    __syncthreads();
#pragma unroll
    for (int off = 1; off < 256; off <<= 1) {
        int v = 0;
        if (tid < 256) {
            v = sScan[tid];
            if (tid >= off) v += sScan[tid - off];
        }
        __syncthreads();
        if (tid < 256) sScan[tid] = v;
        __syncthreads();
    }
    if (tid < 256) {
        int run = sScan[tid] - cnt;   // exclusive prefix count of seps
#pragma unroll
        for (int s = 0; s < 4; s++) {
            if (myids[s] == SEPID) {
                run++;
                if (run <= NN) sBnd[run] = tid * 4 + s;
            }
        }
    }
    __syncthreads();

    // ---------------- 2. segment means -> sX[n*768 + h] ----------------
    // node n tokens: ( (n==0 ? -1 : pos_n), pos_{n+1} ) exclusive of seps.
    if (tid < 384) {
        const float2* f2 = (const float2*)(feat + (size_t)b * S_ * H_);
        const int col = tid;              // float2 column, H/2 = 384
#pragma unroll 1
        for (int n = 0; n < NN; n++) {
            int lo = (n == 0) ? 0 : sBnd[n] + 1;
            int hi = sBnd[n + 1];
            float2 acc = make_float2(0.f, 0.f);
            for (int t = lo; t < hi; t++) {
                float2 v = f2[t * 384 + col];
                acc.x += v.x; acc.y += v.y;
            }
            int c = hi - lo; if (c < 1) c = 1;
            float inv = 1.0f / (float)c;
            sX[n * H_ + col * 2]     = acc.x * inv;
            sX[n * H_ + col * 2 + 1] = acc.y * inv;
        }
    } else {
        // spare threads load bias vectors
        for (int i = tid - 384; i < C_; i += 96) {
            sb1[i] = b1[i]; sbm[i] = bm[i]; sb2[i] = b2[i];
        }
    }
    __syncthreads();

    // ---------------- 3. g[n][c] = sum_h mean[n][h] * W1[h][c] ----------------
    // warps 0..7 compute (warp = n, lane -> 5 cols); W1 k-tiles in sA padded to 160.
    const int warp = tid >> 5, lane = tid & 31;
    const int gc0 = lane * 5;
    float accg[5] = {0.f, 0.f, 0.f, 0.f, 0.f};

    for (int kt = 0; kt < H_ / KT; kt++) {
        for (int i = tid; i < KT * 160; i += NTHR) {
            int k = i / 160;
            int c = i - k * 160;
            sA[i] = (c < C_) ? W1[(kt * KT + k) * C_ + c] : 0.f;
        }
        __syncthreads();
        if (warp < 8) {
            const float4* m4 = (const float4*)(sX + warp * H_ + kt * KT);
#pragma unroll 4
            for (int k4 = 0; k4 < KT / 4; k4++) {
                float4 m = m4[k4];
                const float* wr = sA + (k4 * 4) * 160 + gc0;
#pragma unroll
                for (int j = 0; j < 5; j++) accg[j] += m.x * wr[j];
#pragma unroll
                for (int j = 0; j < 5; j++) accg[j] += m.y * wr[160 + j];
#pragma unroll
                for (int j = 0; j < 5; j++) accg[j] += m.z * wr[320 + j];
#pragma unroll
                for (int j = 0; j < 5; j++) accg[j] += m.w * wr[480 + j];
            }
        }
        __syncthreads();
    }
    if (warp < 8) {
#pragma unroll
        for (int j = 0; j < 5; j++) {
            int c = gc0 + j;
            if (c < C_) sG[warp * C_ + c] = accg[j];
        }
    }

    // ---------------- load Wm, W2 into smem (overwrites W1 tile) ------------
    {
        const float4* wm4 = (const float4*)Wm;
        const float4* w24 = (const float4*)W2;
        float4* a4 = (float4*)sA;
        float4* b4 = (float4*)sB;
        for (int i = tid; i < (C_ * C_) / 4; i += NTHR) {  // 5625 float4
            a4[i] = wm4[i];
            b4[i] = w24[i];
        }
    }
    __syncthreads();

    // ---------------- 4. x[p][c] = relu(g_i - g_j + b1) ---------------------
    const int cg = tid % 30;      // 30 col-groups * 5 = 150
    const int rg = tid / 30;      // 16 row-groups * 4 = 64 pairs
    const int c0 = cg * 5, r0 = rg * 4;
#pragma unroll
    for (int rr = 0; rr < 4; rr++) {
        int p = r0 + rr;
        int i = p >> 3, j = p & 7;
#pragma unroll
        for (int cc = 0; cc < 5; cc++) {
            int c = c0 + cc;
            float v = sG[i * C_ + c] - sG[j * C_ + c] + sb1[c];
            sX[p * 152 + c] = fmaxf(v, 0.f);
        }
    }
    __syncthreads();

    // ---------------- 5a. y = relu(x @ Wm + bm) -----------------------------
    float acc[4][5];
#pragma unroll
    for (int rr = 0; rr < 4; rr++)
#pragma unroll
        for (int cc = 0; cc < 5; cc++) acc[rr][cc] = sbm[c0 + cc];

#pragma unroll 1
    for (int k2 = 0; k2 < C_ / 2; k2++) {
        float2 xv[4];
#pragma unroll
        for (int rr = 0; rr < 4; rr++)
            xv[rr] = *(const float2*)(sX + (r0 + rr) * 152 + 2 * k2);
#pragma unroll
        for (int cc = 0; cc < 5; cc++) {
            float w = sA[(2 * k2) * C_ + c0 + cc];
#pragma unroll
            for (int rr = 0; rr < 4; rr++) acc[rr][cc] += xv[rr].x * w;
        }
#pragma unroll
        for (int cc = 0; cc < 5; cc++) {
            float w = sA[(2 * k2 + 1) * C_ + c0 + cc];
#pragma unroll
            for (int rr = 0; rr < 4; rr++) acc[rr][cc] += xv[rr].y * w;
        }
    }
    __syncthreads();   // all x reads done
#pragma unroll
    for (int rr = 0; rr < 4; rr++)
#pragma unroll
        for (int cc = 0; cc < 5; cc++)
            sX[(r0 + rr) * 152 + c0 + cc] = fmaxf(acc[rr][cc], 0.f);
    __syncthreads();

    // ---------------- 5b. out = y @ W2 + b2 ---------------------------------
#pragma unroll
    for (int rr = 0; rr < 4; rr++)
#pragma unroll
        for (int cc = 0; cc < 5; cc++) acc[rr][cc] = sb2[c0 + cc];

#pragma unroll 1
    for (int k2 = 0; k2 < C_ / 2; k2++) {
        float2 xv[4];
#pragma unroll
        for (int rr = 0; rr < 4; rr++)
            xv[rr] = *(const float2*)(sX + (r0 + rr) * 152 + 2 * k2);
#pragma unroll
        for (int cc = 0; cc < 5; cc++) {
            float w = sB[(2 * k2) * C_ + c0 + cc];
#pragma unroll
            for (int rr = 0; rr < 4; rr++) acc[rr][cc] += xv[rr].x * w;
        }
#pragma unroll
        for (int cc = 0; cc < 5; cc++) {
            float w = sB[(2 * k2 + 1) * C_ + c0 + cc];
#pragma unroll
            for (int rr = 0; rr < 4; rr++) acc[rr][cc] += xv[rr].y * w;
        }
    }

    // out layout [i][j][b][c] : ((p*128 + b)*150 + c)
#pragma unroll
    for (int rr = 0; rr < 4; rr++) {
        int p = r0 + rr;
        float* o = out + ((size_t)p * B_ + b) * C_ + c0;
#pragma unroll
        for (int cc = 0; cc < 5; cc++) o[cc] = acc[rr][cc];
    }
}

extern "C" void kernel_launch(void* const* d_in, const int* in_sizes, int n_in,
                              void* d_out, int out_size)
{
    const int*   ids = (const int*)d_in[0];
    const float* feat = (const float*)d_in[1];
    const float* W1 = (const float*)d_in[2];
    const float* b1 = (const float*)d_in[3];
    const float* Wm = (const float*)d_in[4];
    const float* bm = (const float*)d_in[5];
    const float* W2 = (const float*)d_in[6];
    const float* b2 = (const float*)d_in[7];
    float* out = (float*)d_out;

    cudaFuncSetAttribute(grapher_kernel,
                         cudaFuncAttributeMaxDynamicSharedMemorySize, SMEM_BYTES);
    grapher_kernel<<<B_, NTHR, SMEM_BYTES>>>(ids, feat, W1, b1, Wm, bm, W2, b2, out);
}

// round 3
// speedup vs baseline: 1.4545x; 1.4527x over previous
#include <cuda_runtime.h>
#include <cstdint>

// Grapher: B=128, S=1024, H=768, C=150, N=8, sep id 3. One block per batch.
// fp32 end-to-end with packed f32x2 FFMA (FFMA2), cp.async weight prefetch,
// transposed activation buffer for conflict-free/broadcast smem in the GEMMs.

#define B_   128
#define S_   1024
#define H_   768
#define C_   150
#define NN   8
#define SEPID 3
#define NTHR 608          // 19 warps

// shared memory layout (float offsets)
#define OFF_WM    0        // 150*152 = 22800 (cols 150,151 zero pad)
#define OFF_W2    22800    // 150*152
#define OFF_X     45600    // 9728: meansT[768][8] -> partials[8][8][150] -> XT[152][64]
#define OFF_G     55328    // 8*152
#define OFF_B1    56544    // 152 (pad 0)
#define OFF_BM    56696    // 152
#define OFF_B2    56848    // 152
#define OFF_BND   57000    // 16 ints
#define SMEM_FLOATS 57016
#define SMEM_BYTES (SMEM_FLOATS * 4)   // 228064 <= 232448

typedef unsigned long long u64;

__device__ __forceinline__ uint32_t sptr(const void* p) {
    return (uint32_t)__cvta_generic_to_shared(p);
}
__device__ __forceinline__ void cp8(uint32_t s, const void* g) {
    asm volatile("cp.async.ca.shared.global [%0], [%1], 8;" :: "r"(s), "l"(g));
}
#define CP_COMMIT() asm volatile("cp.async.commit_group;" ::: "memory")
#define CP_WAIT0()  asm volatile("cp.async.wait_group 0;" ::: "memory")

__device__ __forceinline__ void ffma2(u64& d, u64 a, u64 b) {
    asm("fma.rn.f32x2 %0, %1, %2, %0;" : "+l"(d) : "l"(a), "l"(b));
}
__device__ __forceinline__ u64 add2(u64 a, u64 b) {
    u64 r; asm("add.rn.f32x2 %0, %1, %2;" : "=l"(r) : "l"(a), "l"(b)); return r;
}
__device__ __forceinline__ u64 dup2(float x) {
    u64 r; asm("mov.b64 %0, {%1, %1};" : "=l"(r) : "f"(x)); return r;
}
__device__ __forceinline__ u64 pack2(float lo, float hi) {
    u64 r; asm("mov.b64 %0, {%1, %2};" : "=l"(r) : "f"(lo), "f"(hi)); return r;
}
__device__ __forceinline__ void unpack2(u64 v, float& lo, float& hi) {
    asm("mov.b64 {%0, %1}, %2;" : "=f"(lo), "=f"(hi) : "l"(v));
}
__device__ __forceinline__ u64 lds64(uint32_t a) {
    u64 v; asm volatile("ld.shared.u64 %0, [%1];" : "=l"(v) : "r"(a)); return v;
}
__device__ __forceinline__ void lds_v2(uint32_t a, u64& x, u64& y) {
    asm volatile("ld.shared.v2.u64 {%0, %1}, [%2];" : "=l"(x), "=l"(y) : "r"(a));
}
__device__ __forceinline__ void sts64(uint32_t a, u64 v) {
    asm volatile("st.shared.u64 [%0], %1;" :: "r"(a), "l"(v) : "memory");
}

// 64x152 output = XT(150 k) @ W(150x152), warp=8-col group, lane=row pair.
// acc[r][cp]: u64 lanes = (col c0+2cp, c0+2cp+1) for row 2*rg+r.
__device__ __forceinline__ void gemm_pair(uint32_t xt_b, uint32_t w_b, uint32_t bias_b,
                                          int rg, int c0, u64 acc[2][4])
{
#pragma unroll
    for (int cp = 0; cp < 4; cp++) {
        u64 bv = lds64(bias_b + (uint32_t)(c0 + 2 * cp) * 4u);
        acc[0][cp] = bv; acc[1][cp] = bv;
    }
#pragma unroll 6
    for (int k = 0; k < C_; k++) {
        u64 xp = lds64(xt_b + (uint32_t)(k * 64 + 2 * rg) * 4u);
        float x0, x1; unpack2(xp, x0, x1);
        u64 d0 = dup2(x0), d1 = dup2(x1);
        u64 w0, w1, w2, w3;
        uint32_t wa = w_b + (uint32_t)(k * 152 + c0) * 4u;
        lds_v2(wa, w0, w1);
        lds_v2(wa + 16u, w2, w3);
        ffma2(acc[0][0], d0, w0); ffma2(acc[0][1], d0, w1);
        ffma2(acc[0][2], d0, w2); ffma2(acc[0][3], d0, w3);
        ffma2(acc[1][0], d1, w0); ffma2(acc[1][1], d1, w1);
        ffma2(acc[1][2], d1, w2); ffma2(acc[1][3], d1, w3);
    }
}

__global__ __launch_bounds__(NTHR, 1)
void grapher_kernel(const int* __restrict__ ids,
                    const float* __restrict__ feat,
                    const float* __restrict__ W1, const float* __restrict__ b1,
                    const float* __restrict__ Wm, const float* __restrict__ bm,
                    const float* __restrict__ W2, const float* __restrict__ b2,
                    float* __restrict__ out)
{
    extern __shared__ float sm[];
    float* sWm = sm + OFF_WM;
    float* sW2 = sm + OFF_W2;
    float* sX  = sm + OFF_X;      // meansT -> partials -> XT
    float* sG  = sm + OFF_G;
    float* sB1 = sm + OFF_B1;
    float* sBM = sm + OFF_BM;
    float* sB2 = sm + OFF_B2;
    int*   sBnd = (int*)(sm + OFF_BND);

    const int tid = threadIdx.x;
    const int b   = blockIdx.x;
    const uint32_t wm_b = sptr(sWm);
    const uint32_t w2_b = sptr(sW2);
    const uint32_t x_b  = sptr(sX);

    // ---------- cp.async prefetch Wm + W2 (dest stride 152, src 150) ----------
    for (int m = tid; m < C_ * 75; m += NTHR) {
        int r = m / 75, cl = m - r * 75;
        cp8(wm_b + (uint32_t)(r * 152 + 2 * cl) * 4u, Wm + r * C_ + 2 * cl);
        cp8(w2_b + (uint32_t)(r * 152 + 2 * cl) * 4u, W2 + r * C_ + 2 * cl);
    }
    CP_COMMIT();
    if (tid < C_) {                       // zero pad cols 150,151
        sWm[tid * 152 + 150] = 0.f; sWm[tid * 152 + 151] = 0.f;
        sW2[tid * 152 + 150] = 0.f; sW2[tid * 152 + 151] = 0.f;
    }

    // ---------- separator scan (warp 0) ----------
    if (tid < 32) {
        const int lane = tid;
        if (lane < 16) sBnd[lane] = S_;
        __syncwarp();
        const int4* rp = (const int4*)(ids + (size_t)b * S_) + lane * 8;
        int4 v[8];
        int cnt = 0;
#pragma unroll
        for (int q = 0; q < 8; q++) {
            v[q] = rp[q];
            cnt += (v[q].x == SEPID) + (v[q].y == SEPID) +
                   (v[q].z == SEPID) + (v[q].w == SEPID);
        }
        int pre = cnt;
#pragma unroll
        for (int off = 1; off < 32; off <<= 1) {
            int t = __shfl_up_sync(0xffffffffu, pre, off);
            if (lane >= off) pre += t;
        }
        int run = pre - cnt;              // exclusive prefix count
#pragma unroll
        for (int q = 0; q < 8; q++) {
            int base = lane * 32 + q * 4;
            if (v[q].x == SEPID) { run++; if (run <= NN) sBnd[run] = base + 0; }
            if (v[q].y == SEPID) { run++; if (run <= NN) sBnd[run] = base + 1; }
            if (v[q].z == SEPID) { run++; if (run <= NN) sBnd[run] = base + 2; }
            if (v[q].w == SEPID) { run++; if (run <= NN) sBnd[run] = base + 3; }
        }
    } else if (tid >= 448 && tid < 448 + 152) {   // bias vectors (pad 0)
        int i = tid - 448;
        sB1[i] = (i < C_) ? b1[i] : 0.f;
        sBM[i] = (i < C_) ? bm[i] : 0.f;
        sB2[i] = (i < C_) ? b2[i] : 0.f;
    }
    __syncthreads();

    // ---------- segment means -> meansT[k][8] in sX ----------
    if (tid < 384) {
        const float2* f2 = (const float2*)(feat + (size_t)b * S_ * H_) + tid;
#pragma unroll 1
        for (int n = 0; n < NN; n++) {
            int lo = (n == 0) ? 0 : sBnd[n] + 1;
            int hi = sBnd[n + 1];
            float2 a0 = make_float2(0.f, 0.f), a1 = a0, a2 = a0, a3 = a0;
            int t = lo;
            for (; t + 3 < hi; t += 4) {
                float2 v0 = f2[(t + 0) * 384];
                float2 v1 = f2[(t + 1) * 384];
                float2 v2 = f2[(t + 2) * 384];
                float2 v3 = f2[(t + 3) * 384];
                a0.x += v0.x; a0.y += v0.y;
                a1.x += v1.x; a1.y += v1.y;
                a2.x += v2.x; a2.y += v2.y;
                a3.x += v3.x; a3.y += v3.y;
            }
            for (; t < hi; t++) {
                float2 v = f2[t * 384];
                a0.x += v.x; a0.y += v.y;
            }
            float sx = (a0.x + a1.x) + (a2.x + a3.x);
            float sy = (a0.y + a1.y) + (a2.y + a3.y);
            int c = hi - lo; if (c < 1) c = 1;
            float inv = 1.0f / (float)c;
            sX[(2 * tid + 0) * 8 + n] = sx * inv;
            sX[(2 * tid + 1) * 8 + n] = sy * inv;
        }
    }
    __syncthreads();

    // ---------- GEMM1: g[n][c] = sum_k meansT[k][n] * W1[k][c] ----------
    // thread (ks = tid/75, cpair = tid%75), k-slice of 96, cols 2cpair, 2cpair+1.
    u64 g_acc[2][4];
    int ks = 0, cpair = 0;
    if (tid < 600) {
        ks = tid / 75; cpair = tid - ks * 75;
#pragma unroll
        for (int cc = 0; cc < 2; cc++)
#pragma unroll
            for (int q = 0; q < 4; q++) g_acc[cc][q] = 0ull;
        const float2* wrow = (const float2*)(W1 + (size_t)(ks * 96) * C_) + cpair;
#pragma unroll 4
        for (int kk = 0; kk < 96; kk++) {
            int k = ks * 96 + kk;
            float2 w = __ldg(wrow + kk * 75);
            u64 dw0 = dup2(w.x), dw1 = dup2(w.y);
            u64 m01, m23, m45, m67;
            uint32_t ma = x_b + (uint32_t)(k * 8) * 4u;
            lds_v2(ma, m01, m23);
            lds_v2(ma + 16u, m45, m67);
            ffma2(g_acc[0][0], m01, dw0); ffma2(g_acc[0][1], m23, dw0);
            ffma2(g_acc[0][2], m45, dw0); ffma2(g_acc[0][3], m67, dw0);
            ffma2(g_acc[1][0], m01, dw1); ffma2(g_acc[1][1], m23, dw1);
            ffma2(g_acc[1][2], m45, dw1); ffma2(g_acc[1][3], m67, dw1);
        }
    }
    __syncthreads();                      // meansT reads done; reuse region
    if (tid < 600) {                      // partials P[ks][e=cc*4+q][150] (u64 @ 2*cpair)
#pragma unroll
        for (int cc = 0; cc < 2; cc++)
#pragma unroll
            for (int q = 0; q < 4; q++)
                sts64(x_b + (uint32_t)(ks * 1200 + (cc * 4 + q) * 150 + 2 * cpair) * 4u,
                      g_acc[cc][q]);
    }
    __syncthreads();
    if (tid < 600) {                      // reduce 8 slices -> sG
        u64 s = lds64(x_b + (uint32_t)(2 * tid) * 4u);
#pragma unroll
        for (int k8 = 1; k8 < 8; k8++)
            s = add2(s, lds64(x_b + (uint32_t)(k8 * 1200 + 2 * tid) * 4u));
        int e = tid / 75, cp2 = tid - e * 75;
        int cc = e >> 2, q = e & 3, c = 2 * cp2 + cc;
        float lo, hi; unpack2(s, lo, hi);
        sG[(2 * q + 0) * 152 + c] = lo;
        sG[(2 * q + 1) * 152 + c] = hi;
    }
    CP_WAIT0();                           // Wm/W2 resident before GEMM2
    __syncthreads();

    // ---------- pair build: XT[c][p] = relu(g_i[c] - g_j[c] + b1[c]) ----------
    const int cg = tid >> 5;              // warp id 0..18 -> col group of 8
    const int rg = tid & 31;              // row pair 2rg, 2rg+1
    const int c0 = cg * 8;
    {
        float v[2][8];
#pragma unroll
        for (int r = 0; r < 2; r++) {
            int p = 2 * rg + r;
            int i = p >> 3, j = p & 7;
            float4 ga0 = *(const float4*)(sG + i * 152 + c0);
            float4 ga1 = *(const float4*)(sG + i * 152 + c0 + 4);
            float4 gb0 = *(const float4*)(sG + j * 152 + c0);
            float4 gb1 = *(const float4*)(sG + j * 152 + c0 + 4);
            float4 ba  = *(const float4*)(sB1 + c0);
            float4 bb  = *(const float4*)(sB1 + c0 + 4);
            v[r][0] = fmaxf(ga0.x - gb0.x + ba.x, 0.f);
            v[r][1] = fmaxf(ga0.y - gb0.y + ba.y, 0.f);
            v[r][2] = fmaxf(ga0.z - gb0.z + ba.z, 0.f);
            v[r][3] = fmaxf(ga0.w - gb0.w + ba.w, 0.f);
            v[r][4] = fmaxf(ga1.x - gb1.x + bb.x, 0.f);
            v[r][5] = fmaxf(ga1.y - gb1.y + bb.y, 0.f);
            v[r][6] = fmaxf(ga1.z - gb1.z + bb.z, 0.f);
            v[r][7] = fmaxf(ga1.w - gb1.w + bb.w, 0.f);
        }
#pragma unroll
        for (int ccj = 0; ccj < 8; ccj++)
            sts64(x_b + (uint32_t)((c0 + ccj) * 64 + 2 * rg) * 4u,
                  pack2(v[0][ccj], v[1][ccj]));
    }
    __syncthreads();

    // ---------- GEMM2: y = relu(x @ Wm + bm) ----------
    u64 acc[2][4];
    gemm_pair(x_b, wm_b, sptr(sBM), rg, c0, acc);
    __syncthreads();                      // all x reads done
#pragma unroll
    for (int r = 0; r < 2; r++) {
        int p = 2 * rg + r;
#pragma unroll
        for (int cp = 0; cp < 4; cp++) {
            float lo, hi; unpack2(acc[r][cp], lo, hi);
            sX[(c0 + 2 * cp + 0) * 64 + p] = fmaxf(lo, 0.f);
            sX[(c0 + 2 * cp + 1) * 64 + p] = fmaxf(hi, 0.f);
        }
    }
    __syncthreads();

    // ---------- GEMM3: out = y @ W2 + b2 ----------
    gemm_pair(x_b, w2_b, sptr(sB2), rg, c0, acc);

    const int ncp = (cg < 18) ? 4 : 3;    // col group 18 covers 144..149 only
#pragma unroll
    for (int r = 0; r < 2; r++) {
        int p = 2 * rg + r;
        float* o = out + ((size_t)p * B_ + b) * C_ + c0;
        for (int cp = 0; cp < ncp; cp++) {
            float lo, hi; unpack2(acc[r][cp], lo, hi);
            *(float2*)(o + 2 * cp) = make_float2(lo, hi);
        }
    }
}

extern "C" void kernel_launch(void* const* d_in, const int* in_sizes, int n_in,
                              void* d_out, int out_size)
{
    const int*   ids  = (const int*)d_in[0];
    const float* feat = (const float*)d_in[1];
    const float* W1 = (const float*)d_in[2];
    const float* b1 = (const float*)d_in[3];
    const float* Wm = (const float*)d_in[4];
    const float* bm = (const float*)d_in[5];
    const float* W2 = (const float*)d_in[6];
    const float* b2 = (const float*)d_in[7];
    float* out = (float*)d_out;

    cudaFuncSetAttribute(grapher_kernel,
                         cudaFuncAttributeMaxDynamicSharedMemorySize, SMEM_BYTES);
    grapher_kernel<<<B_, NTHR, SMEM_BYTES>>>(ids, feat, W1, b1, Wm, bm, W2, b2, out);
}